// round 6
// baseline (speedup 1.0000x reference)
#include <cuda_runtime.h>
#include <cstdint>

// instant-ngp HashEncoder forward: D=3, L=16, C=2, base=16, scale=2, 2^19 hashmap.
// Levels 0..2 dense, 3..15 hashed (2^19 -> mask).
// R5: push occupancy to 8 blocks/SM (<=32 regs) to saturate the L1tex
// wavefront pipe (measured 88% at occ 70%). Reg trims: no cy/cz arrays,
// rolling float4 output chunk retained.

#define PRIME_Y 2654435761u
#define PRIME_Z 805459861u
#define HASH_MASK 524287u  // 2^19 - 1

__global__ __launch_bounds__(256, 8) void hashenc_fwd(
    const float* __restrict__ inp,   // [B, 3]
    const float* __restrict__ emb,   // [TOTAL_PARAMS * 2] scalar float view
    float* __restrict__ out,         // [B, 32]
    int B)
{
    const int b = blockIdx.x * blockDim.x + threadIdx.x;
    if (b >= B) return;

    const float x = (inp[3 * b + 0] + 1.0f) * 0.5f;
    const float y = (inp[3 * b + 1] + 1.0f) * 0.5f;
    const float z = (inp[3 * b + 2] + 1.0f) * 0.5f;

    // level offsets (in float2 elements); compile-time constants after unroll
    const uint32_t OFF[16] = {
        0u, 4096u, 36864u, 299008u, 823296u, 1347584u, 1871872u, 2396160u,
        2920448u, 3444736u, 3969024u, 4493312u, 5017600u, 5541888u, 6066176u, 6590464u
    };

    float4* o4 = (float4*)(out + (size_t)b * 32);
    float4 chunk;

#pragma unroll
    for (int l = 0; l < 16; ++l) {
        const uint32_t res = 16u << l;
        const float scale = (float)res - 1.0f;

        const float px = x * scale + 0.5f;
        const float py = y * scale + 0.5f;
        const float pz = z * scale + 0.5f;

        const float gx = floorf(px);
        const float gy = floorf(py);
        const float gz = floorf(pz);

        const float tx = px - gx;
        const float ty = py - gy;
        const float tz = pz - gz;

        const uint32_t ix = (uint32_t)gx;
        const uint32_t iy = (uint32_t)gy;
        const uint32_t iz = (uint32_t)gz;

        // base per-dim components; the "+1" variants are computed by a single
        // add at use sites (strength-reduced, no arrays held live)
        uint32_t cy0, cz0, dy, dz;
        if (l < 3) {
            cy0 = iy * res;       dy = res;
            cz0 = iz * res * res; dz = res * res;
        } else {
            cy0 = iy * PRIME_Y;   dy = PRIME_Y;
            cz0 = iz * PRIME_Z;   dz = PRIME_Z;
        }

        const float* lvl = emb + 2u * OFF[l];

        float sx = 0.0f, sy = 0.0f;

        if ((ix & 1u) == 0u) {
            // merged path: both x-corners in one 16B-aligned float4
#pragma unroll
            for (int c = 0; c < 4; ++c) {
                const uint32_t m = (c & 1 ? cy0 + dy : cy0) + 0u;
                const uint32_t n = (c & 2 ? cz0 + dz : cz0) + 0u;
                uint32_t base, sw;
                if (l < 3) {
                    base = ix + m + n;   // even (res even => m,n even)
                    sw = 0u;
                } else {
                    const uint32_t i0 = (ix ^ m ^ n) & HASH_MASK;
                    base = i0 & ~1u;
                    sw = i0 & 1u;
                }
                const float4 g4 = __ldg((const float4*)(lvl + 2u * base));
                float2 g0, g1;
                if (sw) { g0 = make_float2(g4.z, g4.w); g1 = make_float2(g4.x, g4.y); }
                else    { g0 = make_float2(g4.x, g4.y); g1 = make_float2(g4.z, g4.w); }

                const float wyz = (c & 1 ? ty : 1.0f - ty) * (c & 2 ? tz : 1.0f - tz);
                const float w1 = tx * wyz;
                const float w0 = wyz - w1;
                sx = fmaf(w0, g0.x, fmaf(w1, g1.x, sx));
                sy = fmaf(w0, g0.y, fmaf(w1, g1.y, sy));
            }
        } else {
#pragma unroll
            for (int c = 0; c < 4; ++c) {
                const uint32_t m = (c & 1 ? cy0 + dy : cy0) + 0u;
                const uint32_t n = (c & 2 ? cz0 + dz : cz0) + 0u;
                uint32_t i0, i1;
                if (l < 3) {
                    i0 = ix + m + n;
                    i1 = i0 + 1u;
                } else {
                    const uint32_t mm = m ^ n;
                    i0 = (ix        ^ mm) & HASH_MASK;
                    i1 = ((ix + 1u) ^ mm) & HASH_MASK;
                }
                const float2 g0 = __ldg((const float2*)(lvl + 2u * i0));
                const float2 g1 = __ldg((const float2*)(lvl + 2u * i1));

                const float wyz = (c & 1 ? ty : 1.0f - ty) * (c & 2 ? tz : 1.0f - tz);
                const float w1 = tx * wyz;
                const float w0 = wyz - w1;
                sx = fmaf(w0, g0.x, fmaf(w1, g1.x, sx));
                sy = fmaf(w0, g0.y, fmaf(w1, g1.y, sy));
            }
        }

        if (l & 1) {
            chunk.z = sx; chunk.w = sy;
            o4[l >> 1] = chunk;
        } else {
            chunk.x = sx; chunk.y = sy;
        }
    }
}

extern "C" void kernel_launch(void* const* d_in, const int* in_sizes, int n_in,
                              void* d_out, int out_size)
{
    const float* p0 = (const float*)d_in[0];
    const float* p1 = (const float*)d_in[1];
    const float* inp;
    const float* emb;
    int B;
    if (in_sizes[0] < in_sizes[1]) {
        inp = p0; emb = p1; B = in_sizes[0] / 3;
    } else {
        inp = p1; emb = p0; B = in_sizes[1] / 3;
    }
    const int threads = 256;
    const int blocks = (B + threads - 1) / threads;
    hashenc_fwd<<<blocks, threads>>>(inp, emb, (float*)d_out, B);
}

// round 8
// speedup vs baseline: 1.0448x; 1.0448x over previous
#include <cuda_runtime.h>
#include <cstdint>

// instant-ngp HashEncoder forward: D=3, L=16, C=2, base=16, scale=2, 2^19 hashmap.
// Levels 0..2 dense, 3..15 hashed (2^19 -> mask).
// R7: R6 retry with the compilable cache-policy form:
//     - table gathers: createpolicy.fractional.L2::evict_last + ld.global.nc.L2::cache_hint
//     - output: st.global.cs (streaming)
//     - 6 blocks/SM (measured occupancy sweet spot)

#define PRIME_Y 2654435761u
#define PRIME_Z 805459861u
#define HASH_MASK 524287u  // 2^19 - 1

__device__ __forceinline__ uint64_t make_evict_last_policy() {
    uint64_t pol;
    asm("createpolicy.fractional.L2::evict_last.b64 %0, 1.0;" : "=l"(pol));
    return pol;
}
__device__ __forceinline__ float2 ldg_el_f2(const float* p, uint64_t pol) {
    float2 v;
    asm volatile("ld.global.nc.L2::cache_hint.v2.f32 {%0,%1}, [%2], %3;"
                 : "=f"(v.x), "=f"(v.y) : "l"(p), "l"(pol));
    return v;
}
__device__ __forceinline__ float4 ldg_el_f4(const float* p, uint64_t pol) {
    float4 v;
    asm volatile("ld.global.nc.L2::cache_hint.v4.f32 {%0,%1,%2,%3}, [%4], %5;"
                 : "=f"(v.x), "=f"(v.y), "=f"(v.z), "=f"(v.w) : "l"(p), "l"(pol));
    return v;
}
__device__ __forceinline__ void stg_cs_f4(float* p, float4 v) {
    asm volatile("st.global.cs.v4.f32 [%0], {%1,%2,%3,%4};"
                 :: "l"(p), "f"(v.x), "f"(v.y), "f"(v.z), "f"(v.w) : "memory");
}

__global__ __launch_bounds__(256, 6) void hashenc_fwd(
    const float* __restrict__ inp,   // [B, 3]
    const float* __restrict__ emb,   // [TOTAL_PARAMS * 2] scalar float view
    float* __restrict__ out,         // [B, 32]
    int B)
{
    const int b = blockIdx.x * blockDim.x + threadIdx.x;
    if (b >= B) return;

    const uint64_t pol = make_evict_last_policy();

    const float x = (inp[3 * b + 0] + 1.0f) * 0.5f;
    const float y = (inp[3 * b + 1] + 1.0f) * 0.5f;
    const float z = (inp[3 * b + 2] + 1.0f) * 0.5f;

    // level offsets (in float2 elements)
    const uint32_t OFF[16] = {
        0u, 4096u, 36864u, 299008u, 823296u, 1347584u, 1871872u, 2396160u,
        2920448u, 3444736u, 3969024u, 4493312u, 5017600u, 5541888u, 6066176u, 6590464u
    };

    float* obase = out + (size_t)b * 32;
    float4 chunk;

#pragma unroll
    for (int l = 0; l < 16; ++l) {
        const uint32_t res = 16u << l;
        const float scale = (float)res - 1.0f;

        const float px = x * scale + 0.5f;
        const float py = y * scale + 0.5f;
        const float pz = z * scale + 0.5f;

        const float gx = floorf(px);
        const float gy = floorf(py);
        const float gz = floorf(pz);

        const float tx = px - gx;
        const float ty = py - gy;
        const float tz = pz - gz;

        const uint32_t ix = (uint32_t)gx;
        const uint32_t iy = (uint32_t)gy;
        const uint32_t iz = (uint32_t)gz;

        uint32_t cy[2], cz[2];
        if (l < 3) {
            cy[0] = iy * res;       cy[1] = (iy + 1u) * res;
            cz[0] = iz * res * res; cz[1] = (iz + 1u) * (res * res);
        } else {
            cy[0] = iy * PRIME_Y;   cy[1] = (iy + 1u) * PRIME_Y;
            cz[0] = iz * PRIME_Z;   cz[1] = (iz + 1u) * PRIME_Z;
        }

        const float wy[2] = {1.0f - ty, ty};
        const float wz[2] = {1.0f - tz, tz};

        const float* lvl = emb + 2u * OFF[l];

        float sx = 0.0f, sy = 0.0f;

        if ((ix & 1u) == 0u) {
            // merged path: both x-corners in one 16B-aligned float4 (one wavefront)
#pragma unroll
            for (int c = 0; c < 4; ++c) {
                const int by = c & 1, bz = (c >> 1) & 1;
                uint32_t base, sw;
                if (l < 3) {
                    base = ix + cy[by] + cz[bz];   // even
                    sw = 0u;
                } else {
                    const uint32_t i0 = (ix ^ cy[by] ^ cz[bz]) & HASH_MASK;
                    base = i0 & ~1u;
                    sw = i0 & 1u;
                }
                const float4 g4 = ldg_el_f4(lvl + 2u * base, pol);
                float2 g0, g1;
                if (sw) { g0 = make_float2(g4.z, g4.w); g1 = make_float2(g4.x, g4.y); }
                else    { g0 = make_float2(g4.x, g4.y); g1 = make_float2(g4.z, g4.w); }

                const float wyz = wy[by] * wz[bz];
                const float w1 = tx * wyz;
                const float w0 = wyz - w1;
                sx = fmaf(w0, g0.x, fmaf(w1, g1.x, sx));
                sy = fmaf(w0, g0.y, fmaf(w1, g1.y, sy));
            }
        } else {
            const uint32_t ix1 = ix + 1u;
#pragma unroll
            for (int c = 0; c < 4; ++c) {
                const int by = c & 1, bz = (c >> 1) & 1;
                uint32_t i0, i1;
                if (l < 3) {
                    i0 = ix + cy[by] + cz[bz];
                    i1 = i0 + 1u;
                } else {
                    const uint32_t m = cy[by] ^ cz[bz];
                    i0 = (ix  ^ m) & HASH_MASK;
                    i1 = (ix1 ^ m) & HASH_MASK;
                }
                const float2 g0 = ldg_el_f2(lvl + 2u * i0, pol);
                const float2 g1 = ldg_el_f2(lvl + 2u * i1, pol);

                const float wyz = wy[by] * wz[bz];
                const float w1 = tx * wyz;
                const float w0 = wyz - w1;
                sx = fmaf(w0, g0.x, fmaf(w1, g1.x, sx));
                sy = fmaf(w0, g0.y, fmaf(w1, g1.y, sy));
            }
        }

        if (l & 1) {
            chunk.z = sx; chunk.w = sy;
            stg_cs_f4(obase + 4 * (l >> 1), chunk);
        } else {
            chunk.x = sx; chunk.y = sy;
        }
    }
}

extern "C" void kernel_launch(void* const* d_in, const int* in_sizes, int n_in,
                              void* d_out, int out_size)
{
    const float* p0 = (const float*)d_in[0];
    const float* p1 = (const float*)d_in[1];
    const float* inp;
    const float* emb;
    int B;
    if (in_sizes[0] < in_sizes[1]) {
        inp = p0; emb = p1; B = in_sizes[0] / 3;
    } else {
        inp = p1; emb = p0; B = in_sizes[1] / 3;
    }
    const int threads = 256;
    const int blocks = (B + threads - 1) / threads;
    hashenc_fwd<<<blocks, threads>>>(inp, emb, (float*)d_out, B);
}

// round 10
// speedup vs baseline: 1.1471x; 1.0978x over previous
#include <cuda_runtime.h>
#include <cstdint>

// instant-ngp HashEncoder forward: D=3, L=16, C=2, base=16, scale=2, 2^19 hashmap.
// R8: split-level mapping — 8 threads per point, each thread does 2 levels
// (2s, 2s+1) and writes ONE float4 at out[gtid*4]: stores become perfectly
// coalesced (4 wf/warp vs 256 per 32 points). Gather pair-merge retained.

#define PRIME_Y 2654435761u
#define PRIME_Z 805459861u
#define HASH_MASK 524287u  // 2^19 - 1

__device__ __forceinline__ void stg_cs_f4(float* p, float4 v) {
    asm volatile("st.global.cs.v4.f32 [%0], {%1,%2,%3,%4};"
                 :: "l"(p), "f"(v.x), "f"(v.y), "f"(v.z), "f"(v.w) : "memory");
}

__global__ __launch_bounds__(256, 8) void hashenc_fwd(
    const float* __restrict__ inp,   // [B, 3]
    const float* __restrict__ emb,   // [TOTAL_PARAMS * 2] scalar float view
    float* __restrict__ out,         // [B, 32]
    int B)
{
    const int gtid = blockIdx.x * blockDim.x + threadIdx.x;
    const int p = gtid >> 3;       // point index
    const int s = gtid & 7;        // level segment: levels 2s, 2s+1
    if (p >= B) return;

    // 8 lanes share a point -> broadcast loads
    const float x = (__ldg(inp + 3 * p + 0) + 1.0f) * 0.5f;
    const float y = (__ldg(inp + 3 * p + 1) + 1.0f) * 0.5f;
    const float z = (__ldg(inp + 3 * p + 2) + 1.0f) * 0.5f;

    float r[4];

#pragma unroll
    for (int k = 0; k < 2; ++k) {
        const int l = 2 * s + k;
        const uint32_t res = 16u << l;
        const float scale = (float)res - 1.0f;
        const bool dense = (l < 3);

        // level offset in float2 elements:
        // l=0:0, l=1:4096, l=2:36864, l>=3: 299008 + (l-3)*524288
        uint32_t off;
        if (dense) off = (l == 0) ? 0u : (l == 1) ? 4096u : 36864u;
        else       off = 299008u + (uint32_t)(l - 3) * 524288u;

        const float px = x * scale + 0.5f;
        const float py = y * scale + 0.5f;
        const float pz = z * scale + 0.5f;

        const float gx = floorf(px);
        const float gy = floorf(py);
        const float gz = floorf(pz);

        const float tx = px - gx;
        const float ty = py - gy;
        const float tz = pz - gz;

        const uint32_t ix = (uint32_t)gx;
        const uint32_t iy = (uint32_t)gy;
        const uint32_t iz = (uint32_t)gz;

        // per-dim corner components (dense strides vs hash products), selected
        // branchlessly
        const uint32_t dy = dense ? res       : PRIME_Y;
        const uint32_t dz = dense ? res * res : PRIME_Z;
        const uint32_t cy0 = iy * dy, cy1 = cy0 + dy;
        const uint32_t cz0 = iz * dz, cz1 = cz0 + dz;

        const float wy[2] = {1.0f - ty, ty};
        const float wz[2] = {1.0f - tz, tz};

        const float* lvl = emb + 2u * off;

        float sx = 0.0f, sy = 0.0f;

        if ((ix & 1u) == 0u) {
            // merged: both x-corners in one 16B-aligned float4 (one wavefront)
#pragma unroll
            for (int c = 0; c < 4; ++c) {
                const uint32_t my = (c & 1) ? cy1 : cy0;
                const uint32_t mz = (c & 2) ? cz1 : cz0;
                const uint32_t i0 = dense ? (ix + my + mz)
                                          : ((ix ^ my ^ mz) & HASH_MASK);
                const uint32_t base = i0 & ~1u;
                const uint32_t sw = i0 & 1u;   // 0 on dense path (even)

                const float4 g4 = __ldg((const float4*)(lvl + 2u * base));
                float2 g0, g1;
                if (sw) { g0 = make_float2(g4.z, g4.w); g1 = make_float2(g4.x, g4.y); }
                else    { g0 = make_float2(g4.x, g4.y); g1 = make_float2(g4.z, g4.w); }

                const float wyz = wy[c & 1] * wz[(c >> 1) & 1];
                const float w1 = tx * wyz;
                const float w0 = wyz - w1;
                sx = fmaf(w0, g0.x, fmaf(w1, g1.x, sx));
                sy = fmaf(w0, g0.y, fmaf(w1, g1.y, sy));
            }
        } else {
            const uint32_t ix1 = ix + 1u;
#pragma unroll
            for (int c = 0; c < 4; ++c) {
                const uint32_t my = (c & 1) ? cy1 : cy0;
                const uint32_t mz = (c & 2) ? cz1 : cz0;
                uint32_t i0, i1;
                if (dense) {
                    i0 = ix + my + mz;
                    i1 = i0 + 1u;
                } else {
                    const uint32_t m = my ^ mz;
                    i0 = (ix  ^ m) & HASH_MASK;
                    i1 = (ix1 ^ m) & HASH_MASK;
                }
                const float2 g0 = __ldg((const float2*)(lvl + 2u * i0));
                const float2 g1 = __ldg((const float2*)(lvl + 2u * i1));

                const float wyz = wy[c & 1] * wz[(c >> 1) & 1];
                const float w1 = tx * wyz;
                const float w0 = wyz - w1;
                sx = fmaf(w0, g0.x, fmaf(w1, g1.x, sx));
                sy = fmaf(w0, g0.y, fmaf(w1, g1.y, sy));
            }
        }

        r[2 * k + 0] = sx;
        r[2 * k + 1] = sy;
    }

    // one perfectly-coalesced 16B store per thread
    stg_cs_f4((float*)out + (size_t)gtid * 4,
              make_float4(r[0], r[1], r[2], r[3]));
}

extern "C" void kernel_launch(void* const* d_in, const int* in_sizes, int n_in,
                              void* d_out, int out_size)
{
    const float* p0 = (const float*)d_in[0];
    const float* p1 = (const float*)d_in[1];
    const float* inp;
    const float* emb;
    int B;
    if (in_sizes[0] < in_sizes[1]) {
        inp = p0; emb = p1; B = in_sizes[0] / 3;
    } else {
        inp = p1; emb = p0; B = in_sizes[1] / 3;
    }
    const int threads = 256;
    const long long total = (long long)B * 8;
    const int blocks = (int)((total + threads - 1) / threads);
    hashenc_fwd<<<blocks, threads>>>(inp, emb, (float*)d_out, B);
}

// round 11
// speedup vs baseline: 1.1704x; 1.0203x over previous
#include <cuda_runtime.h>
#include <cstdint>

// instant-ngp HashEncoder forward: D=3, L=16, C=2, base=16, scale=2, 2^19 hashmap.
// R10: 16 threads per point, ONE level per thread.
//  - minimal per-thread state (regs ~26) -> near-full occupancy
//  - store = one float2 per lane, fully coalesced (2 wf/warp)
//  - gather pair-merge (even ix -> one float4 per corner pair) retained
//  - .cs streaming stores keep the 128MB output out of L2

#define PRIME_Y 2654435761u
#define PRIME_Z 805459861u
#define HASH_MASK 524287u  // 2^19 - 1

__device__ __forceinline__ void stg_cs_f2(float* p, float2 v) {
    asm volatile("st.global.cs.v2.f32 [%0], {%1,%2};"
                 :: "l"(p), "f"(v.x), "f"(v.y) : "memory");
}

__global__ __launch_bounds__(256) void hashenc_fwd(
    const float* __restrict__ inp,   // [B, 3]
    const float* __restrict__ emb,   // [TOTAL_PARAMS * 2] scalar float view
    float* __restrict__ out,         // [B, 32]
    int B)
{
    const int gtid = blockIdx.x * blockDim.x + threadIdx.x;
    const int p = gtid >> 4;       // point index
    const int l = gtid & 15;       // level index
    if (p >= B) return;

    // 16 lanes share a point -> broadcast loads (2 lines/warp/component)
    const float x = (__ldg(inp + 3 * p + 0) + 1.0f) * 0.5f;
    const float y = (__ldg(inp + 3 * p + 1) + 1.0f) * 0.5f;
    const float z = (__ldg(inp + 3 * p + 2) + 1.0f) * 0.5f;

    const uint32_t res = 16u << l;
    const float scale = (float)res - 1.0f;
    const bool dense = (l < 3);

    // level offset in float2 elements:
    // l=0:0, l=1:4096, l=2:36864, l>=3: 299008 + (l-3)*524288
    uint32_t off;
    if (dense) off = (l == 0) ? 0u : (l == 1) ? 4096u : 36864u;
    else       off = 299008u + (uint32_t)(l - 3) * 524288u;

    const float px = x * scale + 0.5f;
    const float py = y * scale + 0.5f;
    const float pz = z * scale + 0.5f;

    const float gx = floorf(px);
    const float gy = floorf(py);
    const float gz = floorf(pz);

    const float tx = px - gx;
    const float ty = py - gy;
    const float tz = pz - gz;

    const uint32_t ix = (uint32_t)gx;
    const uint32_t iy = (uint32_t)gy;
    const uint32_t iz = (uint32_t)gz;

    // per-dim corner components, branchless dense/hashed select
    const uint32_t dy = dense ? res       : PRIME_Y;
    const uint32_t dz = dense ? res * res : PRIME_Z;
    const uint32_t cy0 = iy * dy, cy1 = cy0 + dy;
    const uint32_t cz0 = iz * dz, cz1 = cz0 + dz;

    const float wy[2] = {1.0f - ty, ty};
    const float wz[2] = {1.0f - tz, tz};

    const float* lvl = emb + 2u * off;

    float sx = 0.0f, sy = 0.0f;

    if ((ix & 1u) == 0u) {
        // merged: both x-corners live in one 16B-aligned float4 (one line)
#pragma unroll
        for (int c = 0; c < 4; ++c) {
            const uint32_t my = (c & 1) ? cy1 : cy0;
            const uint32_t mz = (c & 2) ? cz1 : cz0;
            const uint32_t i0 = dense ? (ix + my + mz)
                                      : ((ix ^ my ^ mz) & HASH_MASK);
            const uint32_t base = i0 & ~1u;
            const uint32_t sw = i0 & 1u;   // 0 on dense path (all terms even)

            const float4 g4 = __ldg((const float4*)(lvl + 2u * base));
            float2 g0, g1;
            if (sw) { g0 = make_float2(g4.z, g4.w); g1 = make_float2(g4.x, g4.y); }
            else    { g0 = make_float2(g4.x, g4.y); g1 = make_float2(g4.z, g4.w); }

            const float wyz = wy[c & 1] * wz[(c >> 1) & 1];
            const float w1 = tx * wyz;
            const float w0 = wyz - w1;
            sx = fmaf(w0, g0.x, fmaf(w1, g1.x, sx));
            sy = fmaf(w0, g0.y, fmaf(w1, g1.y, sy));
        }
    } else {
        const uint32_t ix1 = ix + 1u;
#pragma unroll
        for (int c = 0; c < 4; ++c) {
            const uint32_t my = (c & 1) ? cy1 : cy0;
            const uint32_t mz = (c & 2) ? cz1 : cz0;
            uint32_t i0, i1;
            if (dense) {
                i0 = ix + my + mz;
                i1 = i0 + 1u;
            } else {
                const uint32_t m = my ^ mz;
                i0 = (ix  ^ m) & HASH_MASK;
                i1 = (ix1 ^ m) & HASH_MASK;
            }
            const float2 g0 = __ldg((const float2*)(lvl + 2u * i0));
            const float2 g1 = __ldg((const float2*)(lvl + 2u * i1));

            const float wyz = wy[c & 1] * wz[(c >> 1) & 1];
            const float w1 = tx * wyz;
            const float w0 = wyz - w1;
            sx = fmaf(w0, g0.x, fmaf(w1, g1.x, sx));
            sy = fmaf(w0, g0.y, fmaf(w1, g1.y, sy));
        }
    }

    // one fully-coalesced 8B store per thread: warp writes 2 points x 128B
    stg_cs_f2((float*)out + (size_t)gtid * 2, make_float2(sx, sy));
}

extern "C" void kernel_launch(void* const* d_in, const int* in_sizes, int n_in,
                              void* d_out, int out_size)
{
    const float* p0 = (const float*)d_in[0];
    const float* p1 = (const float*)d_in[1];
    const float* inp;
    const float* emb;
    int B;
    if (in_sizes[0] < in_sizes[1]) {
        inp = p0; emb = p1; B = in_sizes[0] / 3;
    } else {
        inp = p1; emb = p0; B = in_sizes[1] / 3;
    }
    const int threads = 256;
    const long long total = (long long)B * 16;
    const int blocks = (int)((total + threads - 1) / threads);
    hashenc_fwd<<<blocks, threads>>>(inp, emb, (float*)d_out, B);
}